// round 15
// baseline (speedup 1.0000x reference)
#include <cuda_runtime.h>
#include <cuda_bf16.h>
#include <math.h>

#define N_DB   200000
#define D_EMB  512
#define TOP_K  32

// ---- Stage A: pure streaming distances ----
#define TPB_A  256
#define NBLK_A 888                               // 6 CTAs/SM (regs=40 -> occ lim 6)
#define WARPS_A (NBLK_A * (TPB_A / 32))

// histogram: key = float_bits >> 18 (monotone for d >= 0), 8192 bins
#define HSHIFT 18
#define NBINS  8192

// ---- Stage H: histogram build ----
#define TPB_H  1024
#define NBLK_H 148
#define ROWS_H ((N_DB + NBLK_H - 1) / NBLK_H)    // 1352

// ---- Stage C: compact + select + emit (fused tail) ----
#define TPB_C  1024
#define NBLK_C 148
#define ROWS_C ROWS_H
#define BPT    (NBINS / TPB_C)                   // 8 bins per thread
#define CAP    4096

// Scratch (allocation-free rule: __device__ globals; zero-initialized at load)
__device__ float g_dist[N_DB];
__device__ int   g_hist[NBINS];
__device__ int   g_cnt;
__device__ int   g_done;
__device__ float g_cd[CAP];
__device__ int   g_ci[CAP];

// ---------------------------------------------------------------------------
// Stage A: pure streaming. One warp per row; 16 floats/lane in float4s via
// __ldcs (evict-first), shuffle-reduce, lane0 stores squared distance.
// ---------------------------------------------------------------------------
__global__ void __launch_bounds__(TPB_A)
knn_dist(const float* __restrict__ x, const float* __restrict__ emb)
{
    const int lane = threadIdx.x & 31;
    const int gw   = blockIdx.x * (TPB_A / 32) + (threadIdx.x >> 5);

    const float4* x4 = (const float4*)x;
    const float4 q0 = x4[lane];
    const float4 q1 = x4[32 + lane];
    const float4 q2 = x4[64 + lane];
    const float4 q3 = x4[96 + lane];

    for (int r = gw; r < N_DB; r += WARPS_A) {
        const float4* p = (const float4*)(emb + (size_t)r * D_EMB);
        float4 v0 = __ldcs(p + lane);
        float4 v1 = __ldcs(p + 32 + lane);
        float4 v2 = __ldcs(p + 64 + lane);
        float4 v3 = __ldcs(p + 96 + lane);

        float acc, d;
        d = v0.x - q0.x; acc  = d * d;
        d = v0.y - q0.y; acc += d * d;
        d = v0.z - q0.z; acc += d * d;
        d = v0.w - q0.w; acc += d * d;
        d = v1.x - q1.x; acc += d * d;
        d = v1.y - q1.y; acc += d * d;
        d = v1.z - q1.z; acc += d * d;
        d = v1.w - q1.w; acc += d * d;
        d = v2.x - q2.x; acc += d * d;
        d = v2.y - q2.y; acc += d * d;
        d = v2.z - q2.z; acc += d * d;
        d = v2.w - q2.w; acc += d * d;
        d = v3.x - q3.x; acc += d * d;
        d = v3.y - q3.y; acc += d * d;
        d = v3.z - q3.z; acc += d * d;
        d = v3.w - q3.w; acc += d * d;

        #pragma unroll
        for (int o = 16; o > 0; o >>= 1)
            acc += __shfl_down_sync(0xffffffffu, acc, o);
        if (lane == 0) g_dist[r] = acc;
    }
}

// ---------------------------------------------------------------------------
// Stage H: build the global histogram from g_dist (L2-hot, 800 KB).
// ---------------------------------------------------------------------------
__global__ void __launch_bounds__(TPB_H)
knn_hist()
{
    __shared__ int sh[NBINS];                    // 32 KB

    const int tid = threadIdx.x;
    for (int i = tid; i < NBINS; i += TPB_H) sh[i] = 0;
    __syncthreads();

    const int base = blockIdx.x * ROWS_H;
    const int rows = min(ROWS_H, N_DB - base);
    for (int j = tid; j < rows; j += TPB_H) {
        float d = g_dist[base + j];
        atomicAdd(&sh[__float_as_uint(d) >> HSHIFT], 1);
    }
    __syncthreads();

    for (int i = tid; i < NBINS; i += TPB_H) {
        int v = sh[i];
        if (v) atomicAdd(&g_hist[i], v);
    }
}

// ---------------------------------------------------------------------------
// Stage C (fused tail): each block prefix-scans the histogram -> threshold
// bin b*, compacts its slice of g_dist into the candidate buffer. The LAST
// block to finish (done-counter election) then, entirely within itself:
//   1. rank-based exact top-32 over the candidates (smem),
//   2. gathers the 32 neighbor rows (4096 float4, 4 per thread),
//   3. writes cls (cast to float) + sqrt distances,
//   4. re-zeroes all scratch for the next graph replay.
// Output (all float32):
//   [0, 16384)     nbr_emb (32 x 512)
//   [16384, 16416) nbr_cls
//   [16416, 16448) nbr_dist (ascending)
// ---------------------------------------------------------------------------
__global__ void __launch_bounds__(TPB_C)
knn_compact_emit(const float* __restrict__ emb, const int* __restrict__ cls,
                 float* __restrict__ out)
{
    __shared__ int   sp[TPB_C];
    __shared__ int   s_bstar;
    __shared__ int   s_last;
    __shared__ float cd[CAP];
    __shared__ int   ci[CAP];
    __shared__ int   sel_i[TOP_K];
    __shared__ float sel_d[TOP_K];

    const int tid = threadIdx.x;

    int bins[BPT];
    int s = 0;
    const int b0 = tid * BPT;
    #pragma unroll
    for (int i = 0; i < BPT; i++) { bins[i] = g_hist[b0 + i]; s += bins[i]; }

    // Hillis-Steele inclusive scan over 1024 thread sums
    sp[tid] = s;
    __syncthreads();
    int v = s;
    for (int o = 1; o < TPB_C; o <<= 1) {
        int add = (tid >= o) ? sp[tid - o] : 0;
        __syncthreads();
        v += add;
        sp[tid] = v;
        __syncthreads();
    }
    const int excl = v - s;

    if (excl < TOP_K && v >= TOP_K) {
        int cum = excl;
        #pragma unroll
        for (int i = 0; i < BPT; i++) {
            cum += bins[i];
            if (cum >= TOP_K) { s_bstar = b0 + i; break; }
        }
    }
    __syncthreads();
    const unsigned kmax = (unsigned)s_bstar;

    const int base = blockIdx.x * ROWS_C;
    const int rows = min(ROWS_C, N_DB - base);
    for (int j = tid; j < rows; j += TPB_C) {
        float d = g_dist[base + j];
        if ((__float_as_uint(d) >> HSHIFT) <= kmax) {
            int p = atomicAdd(&g_cnt, 1);
            if (p < CAP) { g_cd[p] = d; g_ci[p] = base + j; }
        }
    }
    __syncthreads();

    // last-block election: publish this block's candidate writes, count in.
    if (tid == 0) {
        __threadfence();
        s_last = (atomicAdd(&g_done, 1) == NBLK_C - 1);
    }
    __syncthreads();
    if (!s_last) return;

    // ---- 1. rank selection over ~50 candidates ----
    const int n = min(g_cnt, CAP);
    for (int j = tid; j < n; j += TPB_C) {
        cd[j] = g_cd[j];
        ci[j] = g_ci[j];
    }
    __syncthreads();

    for (int t = tid; t < n; t += TPB_C) {
        float dt = cd[t];
        int   it = ci[t];
        int rank = 0;
        for (int j = 0; j < n; j++) {
            float dj = cd[j];
            int   ij = ci[j];
            rank += (dj < dt || (dj == dt && ij < it)) ? 1 : 0;
        }
        if (rank < TOP_K) { sel_d[rank] = dt; sel_i[rank] = it; }
    }

    // ---- 4a. cleanup (issue early; independent of the gather below) ----
    if (tid == 0) { g_cnt = 0; g_done = 0; }
    {
        int4* h4 = (int4*)g_hist;
        const int4 z = make_int4(0, 0, 0, 0);
        for (int i = tid; i < NBINS / 4; i += TPB_C) h4[i] = z;
    }
    __syncthreads();

    // ---- 2. gather neighbor rows: 4096 float4, 4 per thread (MLP 4) ----
    {
        const float4* emb4 = (const float4*)emb;
        float4*       out4 = (float4*)out;
        #pragma unroll
        for (int i = tid; i < TOP_K * (D_EMB / 4); i += TPB_C) {
            int r = i >> 7;                      // / 128 float4 per row
            int c = i & 127;
            out4[i] = emb4[(size_t)sel_i[r] * (D_EMB / 4) + c];
        }
    }

    // ---- 3. classes + distances ----
    if (tid < TOP_K) {
        out[TOP_K * D_EMB + tid]         = (float)cls[sel_i[tid]];
        out[TOP_K * D_EMB + TOP_K + tid] = sqrtf(sel_d[tid]);
    }
}

extern "C" void kernel_launch(void* const* d_in, const int* in_sizes, int n_in,
                              void* d_out, int out_size)
{
    const float* x   = (const float*)d_in[0];      // [1, 512] f32
    const float* emb = (const float*)d_in[1];      // [200000, 512] f32
    const int*   cls = (const int*)d_in[2];        // [200000] int32
    // d_in[3] is k (scalar), fixed at 32
    float* out = (float*)d_out;

    knn_dist<<<NBLK_A, TPB_A>>>(x, emb);
    knn_hist<<<NBLK_H, TPB_H>>>();
    knn_compact_emit<<<NBLK_C, TPB_C>>>(emb, cls, out);
}

// round 16
// speedup vs baseline: 1.0004x; 1.0004x over previous
#include <cuda_runtime.h>
#include <cuda_bf16.h>
#include <math.h>

#define N_DB   200000
#define D_EMB  512
#define TOP_K  32

// ---- Stage A: pure streaming distances ----
#define TPB_A  256
#define NBLK_A 888                               // 6 CTAs/SM (regs=40 -> occ lim 6)
#define WARPS_A (NBLK_A * (TPB_A / 32))

// histogram: key = float_bits >> 18 (monotone for d >= 0), 8192 bins
#define HSHIFT 18
#define NBINS  8192

// ---- Stage T (fused tail): hist + gridsync + compact + select + emit ----
#define TPB_T  1024
#define NBLK_T 148                               // exactly one wave (1 CTA/SM)
#define ROWS_T ((N_DB + NBLK_T - 1) / NBLK_T)    // 1352
#define BPT    (NBINS / TPB_T)                   // 8 bins per thread
#define CAP    4096

// Scratch (allocation-free rule: __device__ globals; zero-initialized at load)
__device__ float g_dist[N_DB];
__device__ int   g_hist[NBINS];
__device__ int   g_cnt;
__device__ int   g_sync;
__device__ int   g_done;
__device__ float g_cd[CAP];
__device__ int   g_ci[CAP];

// ---------------------------------------------------------------------------
// Stage A: pure streaming (61.8us @ 84% DRAM). One warp per row; 16 floats
// per lane in float4s via __ldcs, shuffle-reduce, lane0 stores dist^2.
// ---------------------------------------------------------------------------
__global__ void __launch_bounds__(TPB_A)
knn_dist(const float* __restrict__ x, const float* __restrict__ emb)
{
    const int lane = threadIdx.x & 31;
    const int gw   = blockIdx.x * (TPB_A / 32) + (threadIdx.x >> 5);

    const float4* x4 = (const float4*)x;
    const float4 q0 = x4[lane];
    const float4 q1 = x4[32 + lane];
    const float4 q2 = x4[64 + lane];
    const float4 q3 = x4[96 + lane];

    for (int r = gw; r < N_DB; r += WARPS_A) {
        const float4* p = (const float4*)(emb + (size_t)r * D_EMB);
        float4 v0 = __ldcs(p + lane);
        float4 v1 = __ldcs(p + 32 + lane);
        float4 v2 = __ldcs(p + 64 + lane);
        float4 v3 = __ldcs(p + 96 + lane);

        float acc, d;
        d = v0.x - q0.x; acc  = d * d;
        d = v0.y - q0.y; acc += d * d;
        d = v0.z - q0.z; acc += d * d;
        d = v0.w - q0.w; acc += d * d;
        d = v1.x - q1.x; acc += d * d;
        d = v1.y - q1.y; acc += d * d;
        d = v1.z - q1.z; acc += d * d;
        d = v1.w - q1.w; acc += d * d;
        d = v2.x - q2.x; acc += d * d;
        d = v2.y - q2.y; acc += d * d;
        d = v2.z - q2.z; acc += d * d;
        d = v2.w - q2.w; acc += d * d;
        d = v3.x - q3.x; acc += d * d;
        d = v3.y - q3.y; acc += d * d;
        d = v3.z - q3.z; acc += d * d;
        d = v3.w - q3.w; acc += d * d;

        #pragma unroll
        for (int o = 16; o > 0; o >>= 1)
            acc += __shfl_down_sync(0xffffffffu, acc, o);
        if (lane == 0) g_dist[r] = acc;
    }
}

// ---------------------------------------------------------------------------
// Stage T: fused tail, single wave (148 blocks = 148 SMs, spin-safe).
//  1. per-block smem histogram of its slice -> merge nonzero bins to g_hist
//  2. grid barrier (release fence + atomic count-in, tid0 spins)
//  3. every block scans g_hist -> threshold bin b*
//  4. compact own slice (key <= b*) into candidate buffer
//  5. last-block election -> rank select + gather + emit + scratch cleanup
// Output (all float32):
//   [0, 16384)     nbr_emb (32 x 512)
//   [16384, 16416) nbr_cls (int32 cast to float)
//   [16416, 16448) nbr_dist (ascending)
// ---------------------------------------------------------------------------
__global__ void __launch_bounds__(TPB_T)
knn_tail(const float* __restrict__ emb, const int* __restrict__ cls,
         float* __restrict__ out)
{
    // histogram (32KB) is dead once merged; overlay candidates (32KB) on it.
    __shared__ char  s_ovl[NBINS * 4];
    __shared__ int   sp[TPB_T];
    __shared__ int   s_bstar;
    __shared__ int   s_last;
    __shared__ int   sel_i[TOP_K];
    __shared__ float sel_d[TOP_K];

    int*   sh = (int*)s_ovl;                     // phase 1: histogram
    float* cd = (float*)s_ovl;                   // phase 5: candidate dists
    int*   ci = (int*)(s_ovl + CAP * 4);         // phase 5: candidate rows

    const int tid  = threadIdx.x;
    const int base = blockIdx.x * ROWS_T;
    const int rows = min(ROWS_T, N_DB - base);

    // ---- 1. histogram own slice ----
    for (int i = tid; i < NBINS; i += TPB_T) sh[i] = 0;
    __syncthreads();
    for (int j = tid; j < rows; j += TPB_T) {
        float d = g_dist[base + j];
        atomicAdd(&sh[__float_as_uint(d) >> HSHIFT], 1);
    }
    __syncthreads();
    for (int i = tid; i < NBINS; i += TPB_T) {
        int v = sh[i];
        if (v) atomicAdd(&g_hist[i], v);
    }
    __syncthreads();

    // ---- 2. grid barrier (one wave -> spin is deadlock-free) ----
    if (tid == 0) {
        __threadfence();
        atomicAdd(&g_sync, 1);
        while (((volatile int*)&g_sync)[0] < NBLK_T) { }
        __threadfence();
    }
    __syncthreads();

    // ---- 3. scan global histogram -> threshold bin b* ----
    int bins[BPT];
    int s = 0;
    const int b0 = tid * BPT;
    #pragma unroll
    for (int i = 0; i < BPT; i++) { bins[i] = g_hist[b0 + i]; s += bins[i]; }

    sp[tid] = s;
    __syncthreads();
    int v = s;
    for (int o = 1; o < TPB_T; o <<= 1) {
        int add = (tid >= o) ? sp[tid - o] : 0;
        __syncthreads();
        v += add;
        sp[tid] = v;
        __syncthreads();
    }
    const int excl = v - s;

    if (excl < TOP_K && v >= TOP_K) {
        int cum = excl;
        #pragma unroll
        for (int i = 0; i < BPT; i++) {
            cum += bins[i];
            if (cum >= TOP_K) { s_bstar = b0 + i; break; }
        }
    }
    __syncthreads();
    const unsigned kmax = (unsigned)s_bstar;

    // ---- 4. compact own slice ----
    for (int j = tid; j < rows; j += TPB_T) {
        float d = g_dist[base + j];
        if ((__float_as_uint(d) >> HSHIFT) <= kmax) {
            int p = atomicAdd(&g_cnt, 1);
            if (p < CAP) { g_cd[p] = d; g_ci[p] = base + j; }
        }
    }
    __syncthreads();

    // ---- 5. last-block election ----
    if (tid == 0) {
        __threadfence();
        s_last = (atomicAdd(&g_done, 1) == NBLK_T - 1);
    }
    __syncthreads();
    if (!s_last) return;

    const int n = min(g_cnt, CAP);
    __syncthreads();                             // histogram smem now dead
    for (int j = tid; j < n; j += TPB_T) {
        cd[j] = g_cd[j];
        ci[j] = g_ci[j];
    }
    __syncthreads();

    // rank selection over ~50 candidates (unique ranks via index tie-break)
    for (int t = tid; t < n; t += TPB_T) {
        float dt = cd[t];
        int   it = ci[t];
        int rank = 0;
        for (int j = 0; j < n; j++) {
            float dj = cd[j];
            int   ij = ci[j];
            rank += (dj < dt || (dj == dt && ij < it)) ? 1 : 0;
        }
        if (rank < TOP_K) { sel_d[rank] = dt; sel_i[rank] = it; }
    }

    // scratch cleanup (independent of gather; issue early)
    if (tid == 0) { g_cnt = 0; g_done = 0; g_sync = 0; }
    {
        int4* h4 = (int4*)g_hist;
        const int4 z = make_int4(0, 0, 0, 0);
        for (int i = tid; i < NBINS / 4; i += TPB_T) h4[i] = z;
    }
    __syncthreads();

    // gather neighbor rows: 4096 float4, 4 per thread (MLP 4)
    {
        const float4* emb4 = (const float4*)emb;
        float4*       out4 = (float4*)out;
        #pragma unroll
        for (int i = tid; i < TOP_K * (D_EMB / 4); i += TPB_T) {
            int r = i >> 7;                      // / 128 float4 per row
            int c = i & 127;
            out4[i] = emb4[(size_t)sel_i[r] * (D_EMB / 4) + c];
        }
    }

    if (tid < TOP_K) {
        out[TOP_K * D_EMB + tid]         = (float)cls[sel_i[tid]];
        out[TOP_K * D_EMB + TOP_K + tid] = sqrtf(sel_d[tid]);
    }
}

extern "C" void kernel_launch(void* const* d_in, const int* in_sizes, int n_in,
                              void* d_out, int out_size)
{
    const float* x   = (const float*)d_in[0];      // [1, 512] f32
    const float* emb = (const float*)d_in[1];      // [200000, 512] f32
    const int*   cls = (const int*)d_in[2];        // [200000] int32
    // d_in[3] is k (scalar), fixed at 32
    float* out = (float*)d_out;

    knn_dist<<<NBLK_A, TPB_A>>>(x, emb);
    knn_tail<<<NBLK_T, TPB_T>>>(emb, cls, out);
}

// round 17
// speedup vs baseline: 1.0189x; 1.0184x over previous
#include <cuda_runtime.h>
#include <cuda_bf16.h>
#include <math.h>

#define N_DB   200000
#define D_EMB  512
#define TOP_K  32

// ---- Stage A: pure streaming distances ----
#define TPB_A  256
#define NBLK_A 888                               // 6 CTAs/SM (regs=40 -> occ lim 6)
#define WARPS_A (NBLK_A * (TPB_A / 32))

// histogram: key = float_bits >> 18 (monotone for d >= 0), 8192 bins
#define HSHIFT 18
#define NBINS  8192

// ---- Stage T (fused tail) ----
#define TPB_T  1024
#define NBLK_T 148                               // exactly one wave (1 CTA/SM)
#define ROWS_T ((N_DB + NBLK_T - 1) / NBLK_T)    // 1352
#define CAP    4096

#define BITS_INF 0x7fffffff

// Scratch (allocation-free rule: __device__ globals)
__device__ float g_dist[N_DB];
__device__ int   g_hist[NBINS];
__device__ int   g_minbits = BITS_INF;
__device__ int   g_cnt;
__device__ int   g_sync;
__device__ int   g_done;
__device__ float g_cd[CAP];
__device__ int   g_ci[CAP];

// ---------------------------------------------------------------------------
// Stage A: pure streaming (61.8us @ 84% DRAM). One warp per row; 16 floats
// per lane in float4s via __ldcs, shuffle-reduce, lane0 stores dist^2.
// ---------------------------------------------------------------------------
__global__ void __launch_bounds__(TPB_A)
knn_dist(const float* __restrict__ x, const float* __restrict__ emb)
{
    const int lane = threadIdx.x & 31;
    const int gw   = blockIdx.x * (TPB_A / 32) + (threadIdx.x >> 5);

    const float4* x4 = (const float4*)x;
    const float4 q0 = x4[lane];
    const float4 q1 = x4[32 + lane];
    const float4 q2 = x4[64 + lane];
    const float4 q3 = x4[96 + lane];

    for (int r = gw; r < N_DB; r += WARPS_A) {
        const float4* p = (const float4*)(emb + (size_t)r * D_EMB);
        float4 v0 = __ldcs(p + lane);
        float4 v1 = __ldcs(p + 32 + lane);
        float4 v2 = __ldcs(p + 64 + lane);
        float4 v3 = __ldcs(p + 96 + lane);

        float acc, d;
        d = v0.x - q0.x; acc  = d * d;
        d = v0.y - q0.y; acc += d * d;
        d = v0.z - q0.z; acc += d * d;
        d = v0.w - q0.w; acc += d * d;
        d = v1.x - q1.x; acc += d * d;
        d = v1.y - q1.y; acc += d * d;
        d = v1.z - q1.z; acc += d * d;
        d = v1.w - q1.w; acc += d * d;
        d = v2.x - q2.x; acc += d * d;
        d = v2.y - q2.y; acc += d * d;
        d = v2.z - q2.z; acc += d * d;
        d = v2.w - q2.w; acc += d * d;
        d = v3.x - q3.x; acc += d * d;
        d = v3.y - q3.y; acc += d * d;
        d = v3.z - q3.z; acc += d * d;
        d = v3.w - q3.w; acc += d * d;

        #pragma unroll
        for (int o = 16; o > 0; o >>= 1)
            acc += __shfl_down_sync(0xffffffffu, acc, o);
        if (lane == 0) g_dist[r] = acc;
    }
}

// ---------------------------------------------------------------------------
// Stage T: fused tail, single wave.
//  1. per-block smem histogram of slice + track block min -> atomicMin
//  2. grid barrier
//  3. walk g_hist forward from bin(g_minbits) until cum >= 32 -> b*
//     (bins below the min's bin are empty; no prefix scan needed)
//  4. compact own slice (key <= b*) into candidate buffer
//  5. last-block election -> rank select + gather + emit + scratch cleanup
// Output (all float32):
//   [0, 16384)     nbr_emb (32 x 512)
//   [16384, 16416) nbr_cls (int32 cast to float)
//   [16416, 16448) nbr_dist (ascending)
// ---------------------------------------------------------------------------
__global__ void __launch_bounds__(TPB_T)
knn_tail(const float* __restrict__ emb, const int* __restrict__ cls,
         float* __restrict__ out)
{
    // histogram (32KB) is dead after the grid sync; overlay candidates on it.
    __shared__ char  s_ovl[NBINS * 4];
    __shared__ int   s_wmin[32];
    __shared__ int   s_bstar;
    __shared__ int   s_last;
    __shared__ int   sel_i[TOP_K];
    __shared__ float sel_d[TOP_K];

    int*   sh = (int*)s_ovl;                     // phase 1: histogram
    float* cd = (float*)s_ovl;                   // phase 5: candidate dists
    int*   ci = (int*)(s_ovl + CAP * 4);         // phase 5: candidate rows

    const int tid  = threadIdx.x;
    const int lane = tid & 31;
    const int wid  = tid >> 5;
    const int base = blockIdx.x * ROWS_T;
    const int rows = min(ROWS_T, N_DB - base);

    // ---- 1. histogram own slice + block min ----
    for (int i = tid; i < NBINS; i += TPB_T) sh[i] = 0;
    __syncthreads();

    int lmin = BITS_INF;
    for (int j = tid; j < rows; j += TPB_T) {
        float d = g_dist[base + j];
        int   b = __float_as_int(d);             // monotone for d >= 0
        atomicAdd(&sh[b >> HSHIFT], 1);
        lmin = min(lmin, b);
    }
    #pragma unroll
    for (int o = 16; o > 0; o >>= 1)
        lmin = min(lmin, __shfl_down_sync(0xffffffffu, lmin, o));
    if (lane == 0) s_wmin[wid] = lmin;
    __syncthreads();

    if (tid == 0) {
        int bm = s_wmin[0];
        #pragma unroll
        for (int w = 1; w < TPB_T / 32; w++) bm = min(bm, s_wmin[w]);
        atomicMin(&g_minbits, bm);
    }
    for (int i = tid; i < NBINS; i += TPB_T) {
        int v = sh[i];
        if (v) atomicAdd(&g_hist[i], v);
    }
    __syncthreads();

    // ---- 2. grid barrier (one wave -> spin is deadlock-free) ----
    if (tid == 0) {
        __threadfence();
        atomicAdd(&g_sync, 1);
        while (((volatile int*)&g_sync)[0] < NBLK_T) { }
        __threadfence();
    }
    __syncthreads();

    // ---- 3. threshold: walk bins from bin(global min) until cum >= 32 ----
    if (tid == 0) {
        int b   = g_minbits >> HSHIFT;           // first nonempty bin
        int cum = 0;
        while (cum < TOP_K && b < NBINS) {
            cum += g_hist[b];
            b++;
        }
        s_bstar = b - 1;
    }
    __syncthreads();
    const unsigned kmax = (unsigned)s_bstar;

    // ---- 4. compact own slice ----
    for (int j = tid; j < rows; j += TPB_T) {
        float d = g_dist[base + j];
        if ((__float_as_uint(d) >> HSHIFT) <= kmax) {
            int p = atomicAdd(&g_cnt, 1);
            if (p < CAP) { g_cd[p] = d; g_ci[p] = base + j; }
        }
    }
    __syncthreads();

    // ---- 5. last-block election ----
    if (tid == 0) {
        __threadfence();
        s_last = (atomicAdd(&g_done, 1) == NBLK_T - 1);
    }
    __syncthreads();
    if (!s_last) return;

    const int n = min(g_cnt, CAP);
    for (int j = tid; j < n; j += TPB_T) {
        cd[j] = g_cd[j];                         // overlays dead histogram
        ci[j] = g_ci[j];
    }
    __syncthreads();

    // rank selection over ~50 candidates (unique ranks via index tie-break)
    for (int t = tid; t < n; t += TPB_T) {
        float dt = cd[t];
        int   it = ci[t];
        int rank = 0;
        for (int j = 0; j < n; j++) {
            float dj = cd[j];
            int   ij = ci[j];
            rank += (dj < dt || (dj == dt && ij < it)) ? 1 : 0;
        }
        if (rank < TOP_K) { sel_d[rank] = dt; sel_i[rank] = it; }
    }

    // scratch cleanup (independent of gather; issue early)
    if (tid == 0) { g_cnt = 0; g_done = 0; g_sync = 0; g_minbits = BITS_INF; }
    {
        int4* h4 = (int4*)g_hist;
        const int4 z = make_int4(0, 0, 0, 0);
        for (int i = tid; i < NBINS / 4; i += TPB_T) h4[i] = z;
    }
    __syncthreads();

    // gather neighbor rows: 4096 float4, 4 per thread (MLP 4)
    {
        const float4* emb4 = (const float4*)emb;
        float4*       out4 = (float4*)out;
        #pragma unroll
        for (int i = tid; i < TOP_K * (D_EMB / 4); i += TPB_T) {
            int r = i >> 7;                      // / 128 float4 per row
            int c = i & 127;
            out4[i] = emb4[(size_t)sel_i[r] * (D_EMB / 4) + c];
        }
    }

    if (tid < TOP_K) {
        out[TOP_K * D_EMB + tid]         = (float)cls[sel_i[tid]];
        out[TOP_K * D_EMB + TOP_K + tid] = sqrtf(sel_d[tid]);
    }
}

extern "C" void kernel_launch(void* const* d_in, const int* in_sizes, int n_in,
                              void* d_out, int out_size)
{
    const float* x   = (const float*)d_in[0];      // [1, 512] f32
    const float* emb = (const float*)d_in[1];      // [200000, 512] f32
    const int*   cls = (const int*)d_in[2];        // [200000] int32
    // d_in[3] is k (scalar), fixed at 32
    float* out = (float*)d_out;

    knn_dist<<<NBLK_A, TPB_A>>>(x, emb);
    knn_tail<<<NBLK_T, TPB_T>>>(emb, cls, out);
}